// round 15
// baseline (speedup 1.0000x reference)
#include <cuda_runtime.h>
#include <cuda_bf16.h>
#include <cstdint>

// ---------------- problem sizes ----------------
#define BATCH 8
#define NN    2048
#define KDIM  256
#define NV    (BATCH * NN * KDIM)   // 4,194,304 v elems
#define NW    (256 * 256)           // W elems

// bf16 hi/lo splits of inputs and projections.
__device__ __align__(16) __nv_bfloat16 g_vhi[NV],  g_vlo[NV];
__device__ __align__(16) __nv_bfloat16 g_w1hi[NW], g_w1lo[NW];
__device__ __align__(16) __nv_bfloat16 g_w2hi[NW], g_w2lo[NW];
__device__ __align__(16) __nv_bfloat16 g_c1hi[NV], g_c1lo[NV];
__device__ __align__(16) __nv_bfloat16 g_c2hi[NV], g_c2lo[NV];

// ---------------- helpers ----------------
__device__ __forceinline__ uint32_t smem_u32(const void* p) {
    uint32_t a;
    asm("{ .reg .u64 t; cvta.to.shared.u64 t, %1; cvt.u32.u64 %0, t; }"
        : "=r"(a) : "l"(p));
    return a;
}

#define SW128(off) ((off) ^ (((off) >> 3) & 0x70))   // 128B-row swizzle
#define SW64(off)  ((off) ^ (((off) >> 3) & 0x30))   // 64B-row swizzle

__device__ __forceinline__ void ldsm_x4(uint32_t (&r)[4], uint32_t addr) {
    asm volatile("ldmatrix.sync.aligned.m8n8.x4.shared.b16 {%0,%1,%2,%3}, [%4];"
        : "=r"(r[0]), "=r"(r[1]), "=r"(r[2]), "=r"(r[3]) : "r"(addr));
}
__device__ __forceinline__ void ldsm_x2(uint32_t (&r)[2], uint32_t addr) {
    asm volatile("ldmatrix.sync.aligned.m8n8.x2.shared.b16 {%0,%1}, [%2];"
        : "=r"(r[0]), "=r"(r[1]) : "r"(addr));
}
__device__ __forceinline__ void mma_bf16(float (&d)[4], const uint32_t (&a)[4],
                                         const uint32_t b0, const uint32_t b1) {
    asm volatile(
        "mma.sync.aligned.m16n8k16.row.col.f32.bf16.bf16.f32 "
        "{%0,%1,%2,%3}, {%4,%5,%6,%7}, {%8,%9}, {%0,%1,%2,%3};"
        : "+f"(d[0]), "+f"(d[1]), "+f"(d[2]), "+f"(d[3])
        : "r"(a[0]), "r"(a[1]), "r"(a[2]), "r"(a[3]), "r"(b0), "r"(b1));
}
__device__ __forceinline__ void cp_async16(uint32_t dst, const void* src) {
    asm volatile("cp.async.cg.shared.global [%0], [%1], 16;" :: "r"(dst), "l"(src));
}
#define CP_COMMIT() asm volatile("cp.async.commit_group;" ::: "memory")
#define CP_WAIT1()  asm volatile("cp.async.wait_group 1;" ::: "memory")
#define CP_WAIT0()  asm volatile("cp.async.wait_group 0;" ::: "memory")

// ---------------- elementwise epilogue (3 MUFU) ----------------
__device__ __forceinline__ float epi(float s, float a) {
    float t = __expf(fminf(-s, 80.0f));
    float u = 1.0f + t;
    float q = __fdividef(u, fmaf(1e-5f, u, 100.0f));
    q *= 0.70710678f;
    float cc = q * q;                  // = 1/(2 c^2)
    return __expf(-(a * a * cc));
}

__device__ __forceinline__ void split_store(__nv_bfloat16* hi, __nv_bfloat16* lo,
                                            int t, float4 x) {
    float xs[4] = {x.x, x.y, x.z, x.w};
    __nv_bfloat16 h[4], l[4];
#pragma unroll
    for (int j = 0; j < 4; j++) {
        h[j] = __float2bfloat16(xs[j]);
        l[j] = __float2bfloat16(xs[j] - __bfloat162float(h[j]));
    }
    *(__nv_bfloat162*)(hi + 4 * t)     = __nv_bfloat162(h[0], h[1]);
    *(__nv_bfloat162*)(hi + 4 * t + 2) = __nv_bfloat162(h[2], h[3]);
    *(__nv_bfloat162*)(lo + 4 * t)     = __nv_bfloat162(l[0], l[1]);
    *(__nv_bfloat162*)(lo + 4 * t + 2) = __nv_bfloat162(l[2], l[3]);
}

// ---------------------------------------------------------------------------
// Split kernel: v -> (g_vhi, g_vlo) + v passthrough copy; W1/W2 -> splits.
// ---------------------------------------------------------------------------
__global__ __launch_bounds__(256) void split_kernel(
    const float* __restrict__ v,
    const float* __restrict__ W1,
    const float* __restrict__ W2,
    float* __restrict__ out_v)
{
    const int NV4 = NV / 4, NW4 = NW / 4;
    int t = blockIdx.x * 256 + threadIdx.x;
    if (t < NV4) {
        float4 x = ((const float4*)v)[t];
        if (out_v) ((float4*)out_v)[t] = x;
        split_store(g_vhi, g_vlo, t, x);
    } else if (t < NV4 + NW4) {
        int i = t - NV4;
        split_store(g_w1hi, g_w1lo, i, ((const float4*)W1)[i]);
    } else if (t < NV4 + 2 * NW4) {
        int i = t - NV4 - NW4;
        split_store(g_w2hi, g_w2lo, i, ((const float4*)W2)[i]);
    }
}

// ---------------------------------------------------------------------------
// Projection via mma.sync (3-term bf16): c = v @ W^T, K=256.
// CTA 128 rows x 64 cols, 8 warps (2x4), warp tile 64x16 (4x2 m16n8k16).
// KCH=64, SW128 rows, double-buffered cp.async. 2 CTAs/SM.
// ---------------------------------------------------------------------------
#define PKCH 64
#define PSM_BUF(b) ((b) * 49152)
#define PSM_A_HI(b) (PSM_BUF(b) + 0)
#define PSM_A_LO(b) (PSM_BUF(b) + 16384)
#define PSM_B_HI(b) (PSM_BUF(b) + 32768)
#define PSM_B_LO(b) (PSM_BUF(b) + 40960)
#define PSM_TOTAL   (2 * 49152)

__global__ __launch_bounds__(256, 2) void proj_kernel()
{
    extern __shared__ __align__(1024) char smem[];
    uint32_t sm = smem_u32(smem);
    int tid = threadIdx.x;
    int wid = tid >> 5, lid = tid & 31;
    int row0 = blockIdx.x * 128;          // v rows
    int n0 = blockIdx.y * 64;             // output features
    int which = blockIdx.z;

    const __nv_bfloat16* Ahi = g_vhi + (size_t)row0 * KDIM;
    const __nv_bfloat16* Alo = g_vlo + (size_t)row0 * KDIM;
    const __nv_bfloat16* Bhi = (which ? g_w2hi : g_w1hi) + (size_t)n0 * KDIM;
    const __nv_bfloat16* Blo = (which ? g_w2lo : g_w1lo) + (size_t)n0 * KDIM;
    __nv_bfloat16* Chi = which ? g_c2hi : g_c1hi;
    __nv_bfloat16* Clo = which ? g_c2lo : g_c1lo;

    auto fill = [&](int buf, int ch) {
        int k0 = ch * PKCH;
        // A tiles: 128 rows x 64 bf16 each (hi, lo) -> 4 x 16B per thread each.
#pragma unroll
        for (int r = 0; r < 4; r++) {
            int idx = r * 256 + tid;          // 0..1023
            int row = idx >> 3, col = (idx & 7) * 8;
            uint32_t off = SW128((uint32_t)(row * 128 + col * 2));
            cp_async16(sm + PSM_A_HI(buf) + off, Ahi + (size_t)row * KDIM + k0 + col);
            cp_async16(sm + PSM_A_LO(buf) + off, Alo + (size_t)row * KDIM + k0 + col);
        }
        // B tiles: 64 rows x 64 bf16 each -> 2 x 16B per thread each.
#pragma unroll
        for (int r = 0; r < 2; r++) {
            int idx = r * 256 + tid;          // 0..511
            int row = idx >> 3, col = (idx & 7) * 8;
            uint32_t off = SW128((uint32_t)(row * 128 + col * 2));
            cp_async16(sm + PSM_B_HI(buf) + off, Bhi + (size_t)row * KDIM + k0 + col);
            cp_async16(sm + PSM_B_LO(buf) + off, Blo + (size_t)row * KDIM + k0 + col);
        }
        CP_COMMIT();
    };

    float acc[4][2][4];
#pragma unroll
    for (int mt = 0; mt < 4; mt++)
#pragma unroll
        for (int nt = 0; nt < 2; nt++)
#pragma unroll
            for (int r = 0; r < 4; r++) acc[mt][nt][r] = 0.0f;

    int wr = wid >> 2;      // 0..1 : 64-row block
    int wc = wid & 3;       // 0..3 : 16-col block
    int lt = lid >> 3, lr = lid & 7;

    fill(0, 0);
    for (int ch = 0; ch < 4; ch++) {
        int buf = ch & 1;
        if (ch < 3) fill(buf ^ 1, ch + 1);
        if (ch < 3) CP_WAIT1(); else CP_WAIT0();
        __syncthreads();

#pragma unroll
        for (int ks = 0; ks < 4; ks++) {
            int k0 = ks * 16;
            uint32_t Ah[4][4], Al[4][4];
#pragma unroll
            for (int mt = 0; mt < 4; mt++) {
                uint32_t off = SW128((uint32_t)(
                    (wr * 64 + mt * 16 + (lt & 1) * 8 + lr) * 128 +
                    (k0 + (lt >> 1) * 8) * 2));
                ldsm_x4(Ah[mt], sm + PSM_A_HI(buf) + off);
                ldsm_x4(Al[mt], sm + PSM_A_LO(buf) + off);
            }
            uint32_t Bh[2][2], Bl[2][2];
#pragma unroll
            for (int nt = 0; nt < 2; nt++) {
                uint32_t off = SW128((uint32_t)(
                    (wc * 16 + nt * 8 + lr) * 128 + (k0 + (lt & 1) * 8) * 2));
                ldsm_x2(Bh[nt], sm + PSM_B_HI(buf) + off);
                ldsm_x2(Bl[nt], sm + PSM_B_LO(buf) + off);
            }
#pragma unroll
            for (int mt = 0; mt < 4; mt++)
#pragma unroll
                for (int nt = 0; nt < 2; nt++) {
                    mma_bf16(acc[mt][nt], Ah[mt], Bh[nt][0], Bh[nt][1]);
                    mma_bf16(acc[mt][nt], Ah[mt], Bl[nt][0], Bl[nt][1]);
                    mma_bf16(acc[mt][nt], Al[mt], Bh[nt][0], Bh[nt][1]);
                }
        }
        __syncthreads();
    }

    // Epilogue: split c into bf16 hi/lo and store.
    int Rb = wr * 64 + (lid >> 2);
    int Cb = wc * 16 + (lid & 3) * 2;
#pragma unroll
    for (int mt = 0; mt < 4; mt++)
#pragma unroll
        for (int h = 0; h < 2; h++) {
            size_t row = (size_t)(row0 + Rb + mt * 16 + h * 8) * KDIM;
#pragma unroll
            for (int nt = 0; nt < 2; nt++) {
                size_t o = row + n0 + Cb + nt * 8;
                float c0 = acc[mt][nt][h * 2 + 0];
                float c1 = acc[mt][nt][h * 2 + 1];
                __nv_bfloat16 h0 = __float2bfloat16(c0);
                __nv_bfloat16 h1 = __float2bfloat16(c1);
                __nv_bfloat16 l0 = __float2bfloat16(c0 - __bfloat162float(h0));
                __nv_bfloat16 l1 = __float2bfloat16(c1 - __bfloat162float(h1));
                *(__nv_bfloat162*)(Chi + o) = __nv_bfloat162(h0, h1);
                *(__nv_bfloat162*)(Clo + o) = __nv_bfloat162(l0, l1);
            }
        }
}

// ---------------------------------------------------------------------------
// Score GEMM (3-term bf16 mma.sync) + fused epilogue.
// CTA 64(n) x 128(m), 128 threads (4 warps), warp tile 64x32.
// KCH=32, SW64 rows (64B). SMEM 2 bufs x 24KB = 48KB -> 3 CTAs/SM.
// ---------------------------------------------------------------------------
#define SKCH 32
#define SSM_BUF(b)  ((b) * 24576)
#define SSM_A_HI(b) (SSM_BUF(b) + 0)
#define SSM_A_LO(b) (SSM_BUF(b) + 4096)
#define SSM_B_HI(b) (SSM_BUF(b) + 8192)
#define SSM_B_LO(b) (SSM_BUF(b) + 16384)
#define SSM_TOTAL   (2 * 24576)

__global__ __launch_bounds__(128, 3) void score_kernel(
    const float* __restrict__ adj,
    float* __restrict__ out)
{
    extern __shared__ __align__(1024) char smem[];
    uint32_t sm = smem_u32(smem);
    int tid = threadIdx.x;
    int wid = tid >> 5, lid = tid & 31;
    int b = blockIdx.z;
    int n0 = blockIdx.x * 64;      // output rows
    int m0 = blockIdx.y * 128;     // output cols

    const size_t boff = (size_t)b * NN * KDIM;
    const __nv_bfloat16* Ahi = g_c1hi + boff + (size_t)n0 * KDIM;
    const __nv_bfloat16* Alo = g_c1lo + boff + (size_t)n0 * KDIM;
    const __nv_bfloat16* Bhi = g_c2hi + boff + (size_t)m0 * KDIM;
    const __nv_bfloat16* Blo = g_c2lo + boff + (size_t)m0 * KDIM;

    auto fill = [&](int buf, int ch) {
        int k0 = ch * SKCH;
        // A tiles: 64 rows x 32 bf16 (64B rows) -> 256 granules -> 2/thread.
#pragma unroll
        for (int r = 0; r < 2; r++) {
            int idx = r * 128 + tid;          // 0..255
            int row = idx >> 2, col = (idx & 3) * 8;
            uint32_t off = SW64((uint32_t)(row * 64 + col * 2));
            cp_async16(sm + SSM_A_HI(buf) + off, Ahi + (size_t)row * KDIM + k0 + col);
            cp_async16(sm + SSM_A_LO(buf) + off, Alo + (size_t)row * KDIM + k0 + col);
        }
        // B tiles: 128 rows x 32 bf16 -> 512 granules -> 4/thread.
#pragma unroll
        for (int r = 0; r < 4; r++) {
            int idx = r * 128 + tid;          // 0..511
            int row = idx >> 2, col = (idx & 3) * 8;
            uint32_t off = SW64((uint32_t)(row * 64 + col * 2));
            cp_async16(sm + SSM_B_HI(buf) + off, Bhi + (size_t)row * KDIM + k0 + col);
            cp_async16(sm + SSM_B_LO(buf) + off, Blo + (size_t)row * KDIM + k0 + col);
        }
        CP_COMMIT();
    };

    float acc[4][4][4];
#pragma unroll
    for (int mt = 0; mt < 4; mt++)
#pragma unroll
        for (int nt = 0; nt < 4; nt++)
#pragma unroll
            for (int r = 0; r < 4; r++) acc[mt][nt][r] = 0.0f;

    int wc = wid;           // 0..3 : 32-col block
    int lt = lid >> 3, lr = lid & 7;

    fill(0, 0);
    for (int ch = 0; ch < 8; ch++) {
        int buf = ch & 1;
        if (ch < 7) fill(buf ^ 1, ch + 1);
        if (ch < 7) CP_WAIT1(); else CP_WAIT0();
        __syncthreads();

#pragma unroll
        for (int ks = 0; ks < 2; ks++) {
            int k0 = ks * 16;
            uint32_t Ah[4][4], Al[4][4];
#pragma unroll
            for (int mt = 0; mt < 4; mt++) {
                uint32_t off = SW64((uint32_t)(
                    (mt * 16 + (lt & 1) * 8 + lr) * 64 +
                    (k0 + (lt >> 1) * 8) * 2));
                ldsm_x4(Ah[mt], sm + SSM_A_HI(buf) + off);
                ldsm_x4(Al[mt], sm + SSM_A_LO(buf) + off);
            }
            uint32_t Bh[4][2], Bl[4][2];
#pragma unroll
            for (int nt = 0; nt < 4; nt++) {
                uint32_t off = SW64((uint32_t)(
                    (wc * 32 + nt * 8 + lr) * 64 + (k0 + (lt & 1) * 8) * 2));
                ldsm_x2(Bh[nt], sm + SSM_B_HI(buf) + off);
                ldsm_x2(Bl[nt], sm + SSM_B_LO(buf) + off);
            }
#pragma unroll
            for (int mt = 0; mt < 4; mt++)
#pragma unroll
                for (int nt = 0; nt < 4; nt++) {
                    mma_bf16(acc[mt][nt], Ah[mt], Bh[nt][0], Bh[nt][1]);
                    mma_bf16(acc[mt][nt], Ah[mt], Bl[nt][0], Bl[nt][1]);
                    mma_bf16(acc[mt][nt], Al[mt], Bh[nt][0], Bh[nt][1]);
                }
        }
        __syncthreads();
    }

    // Fused epilogue straight from accumulators.
    const float* adj_b = adj + ((size_t)b * NN + n0) * NN + m0;
    float* out_b = out + ((size_t)b * NN + n0) * NN + m0;
    int Rb = lid >> 2;
    int Cb = wc * 32 + (lid & 3) * 2;
#pragma unroll
    for (int mt = 0; mt < 4; mt++) {
#pragma unroll
        for (int h = 0; h < 2; h++) {
            size_t row = (size_t)(Rb + mt * 16 + h * 8) * NN;
#pragma unroll
            for (int nt = 0; nt < 4; nt++) {
                size_t o = row + Cb + nt * 8;
                float2 a2 = *(const float2*)(adj_b + o);
                float2 r;
                r.x = epi(acc[mt][nt][h * 2 + 0], a2.x);
                r.y = epi(acc[mt][nt][h * 2 + 1], a2.y);
                *(float2*)(out_b + o) = r;
            }
        }
    }
}

extern "C" void kernel_launch(void* const* d_in, const int* in_sizes, int n_in,
                              void* d_out, int out_size) {
    const float* v   = (const float*)d_in[0];
    const float* adj = (const float*)d_in[1];
    const float* W1  = (const float*)d_in[2];
    const float* W2  = (const float*)d_in[3];
    float* out = (float*)d_out;

    const long adj_elems = 8L * 2048 * 2048;
    long off = (long)out_size - adj_elems;
    if (off < 0) off = 0;
    float* norm_adj = out + off;
    float* out_v = (off > 0) ? out : nullptr;

    // 1. Split v/W into bf16 hi/lo (+ v passthrough copy).
    int split_ctas = (NV / 4 + 2 * (NW / 4) + 255) / 256;
    split_kernel<<<split_ctas, 256>>>(v, W1, W2, out_v);

    // 2. Projections via mma.sync -> g_c{1,2}{hi,lo}.
    cudaFuncSetAttribute(proj_kernel,
                         cudaFuncAttributeMaxDynamicSharedMemorySize, PSM_TOTAL);
    dim3 pgrid(16384 / 128, 256 / 64, 2);
    proj_kernel<<<pgrid, 256, PSM_TOTAL>>>();

    // 3. Score GEMM + fused epilogue (3 CTAs/SM).
    cudaFuncSetAttribute(score_kernel,
                         cudaFuncAttributeMaxDynamicSharedMemorySize, SSM_TOTAL);
    dim3 sgrid(NN / 64, NN / 128, BATCH);
    score_kernel<<<sgrid, 128, SSM_TOTAL>>>(adj, norm_adj);
}

// round 16
// speedup vs baseline: 1.4968x; 1.4968x over previous
#include <cuda_runtime.h>
#include <cuda_bf16.h>
#include <cstdint>

// ---------------- problem sizes ----------------
#define BATCH 8
#define NN    2048
#define KDIM  256
#define NV    (BATCH * NN * KDIM)   // 4,194,304 v elems
#define NW    (256 * 256)           // W elems

// bf16 hi/lo splits of inputs and projections.
__device__ __align__(16) __nv_bfloat16 g_vhi[NV],  g_vlo[NV];
__device__ __align__(16) __nv_bfloat16 g_w1hi[NW], g_w1lo[NW];
__device__ __align__(16) __nv_bfloat16 g_w2hi[NW], g_w2lo[NW];
__device__ __align__(16) __nv_bfloat16 g_c1hi[NV], g_c1lo[NV];
__device__ __align__(16) __nv_bfloat16 g_c2hi[NV], g_c2lo[NV];

// ---------------- helpers ----------------
__device__ __forceinline__ uint32_t smem_u32(const void* p) {
    uint32_t a;
    asm("{ .reg .u64 t; cvta.to.shared.u64 t, %1; cvt.u32.u64 %0, t; }"
        : "=r"(a) : "l"(p));
    return a;
}

#define SW128(off) ((off) ^ (((off) >> 3) & 0x70))   // 128B-row swizzle
#define SW64(off)  ((off) ^ (((off) >> 3) & 0x30))   // 64B-row swizzle

__device__ __forceinline__ void ldsm_x4(uint32_t (&r)[4], uint32_t addr) {
    asm volatile("ldmatrix.sync.aligned.m8n8.x4.shared.b16 {%0,%1,%2,%3}, [%4];"
        : "=r"(r[0]), "=r"(r[1]), "=r"(r[2]), "=r"(r[3]) : "r"(addr));
}
__device__ __forceinline__ void ldsm_x2(uint32_t (&r)[2], uint32_t addr) {
    asm volatile("ldmatrix.sync.aligned.m8n8.x2.shared.b16 {%0,%1}, [%2];"
        : "=r"(r[0]), "=r"(r[1]) : "r"(addr));
}
__device__ __forceinline__ void mma_bf16(float (&d)[4], const uint32_t (&a)[4],
                                         const uint32_t b0, const uint32_t b1) {
    asm volatile(
        "mma.sync.aligned.m16n8k16.row.col.f32.bf16.bf16.f32 "
        "{%0,%1,%2,%3}, {%4,%5,%6,%7}, {%8,%9}, {%0,%1,%2,%3};"
        : "+f"(d[0]), "+f"(d[1]), "+f"(d[2]), "+f"(d[3])
        : "r"(a[0]), "r"(a[1]), "r"(a[2]), "r"(a[3]), "r"(b0), "r"(b1));
}
__device__ __forceinline__ void cp_async16(uint32_t dst, const void* src) {
    asm volatile("cp.async.cg.shared.global [%0], [%1], 16;" :: "r"(dst), "l"(src));
}
#define CP_COMMIT() asm volatile("cp.async.commit_group;" ::: "memory")
#define CP_WAIT1()  asm volatile("cp.async.wait_group 1;" ::: "memory")
#define CP_WAIT0()  asm volatile("cp.async.wait_group 0;" ::: "memory")

// ---------------- elementwise epilogue (3 MUFU) ----------------
__device__ __forceinline__ float epi(float s, float a) {
    float t = __expf(fminf(-s, 80.0f));
    float u = 1.0f + t;
    float q = __fdividef(u, fmaf(1e-5f, u, 100.0f));
    q *= 0.70710678f;
    float cc = q * q;                  // = 1/(2 c^2)
    return __expf(-(a * a * cc));
}

__device__ __forceinline__ void split_store(__nv_bfloat16* hi, __nv_bfloat16* lo,
                                            int t, float4 x) {
    float xs[4] = {x.x, x.y, x.z, x.w};
    __nv_bfloat16 h[4], l[4];
#pragma unroll
    for (int j = 0; j < 4; j++) {
        h[j] = __float2bfloat16(xs[j]);
        l[j] = __float2bfloat16(xs[j] - __bfloat162float(h[j]));
    }
    *(__nv_bfloat162*)(hi + 4 * t)     = __nv_bfloat162(h[0], h[1]);
    *(__nv_bfloat162*)(hi + 4 * t + 2) = __nv_bfloat162(h[2], h[3]);
    *(__nv_bfloat162*)(lo + 4 * t)     = __nv_bfloat162(l[0], l[1]);
    *(__nv_bfloat162*)(lo + 4 * t + 2) = __nv_bfloat162(l[2], l[3]);
}

// ---------------------------------------------------------------------------
// Split kernel: v -> (g_vhi, g_vlo) + v passthrough copy; W1/W2 -> splits.
// (Also serves as the machine-state control: fixed 100MB traffic, ~9.5us
// on a healthy container.)
// ---------------------------------------------------------------------------
__global__ __launch_bounds__(256) void split_kernel(
    const float* __restrict__ v,
    const float* __restrict__ W1,
    const float* __restrict__ W2,
    float* __restrict__ out_v)
{
    const int NV4 = NV / 4, NW4 = NW / 4;
    int t = blockIdx.x * 256 + threadIdx.x;
    if (t < NV4) {
        float4 x = ((const float4*)v)[t];
        if (out_v) ((float4*)out_v)[t] = x;
        split_store(g_vhi, g_vlo, t, x);
    } else if (t < NV4 + NW4) {
        int i = t - NV4;
        split_store(g_w1hi, g_w1lo, i, ((const float4*)W1)[i]);
    } else if (t < NV4 + 2 * NW4) {
        int i = t - NV4 - NW4;
        split_store(g_w2hi, g_w2lo, i, ((const float4*)W2)[i]);
    }
}

// ---------------------------------------------------------------------------
// Projection via mma.sync (3-term bf16): c = v @ W^T, K=256.
// CTA 128 rows x 64 cols, 8 warps (2x4), warp tile 64x16 (4x2 m16n8k16).
// KCH=64, SW128 rows, double-buffered cp.async. 2 CTAs/SM.
// ---------------------------------------------------------------------------
#define PKCH 64
#define PSM_BUF(b) ((b) * 49152)
#define PSM_A_HI(b) (PSM_BUF(b) + 0)
#define PSM_A_LO(b) (PSM_BUF(b) + 16384)
#define PSM_B_HI(b) (PSM_BUF(b) + 32768)
#define PSM_B_LO(b) (PSM_BUF(b) + 40960)
#define PSM_TOTAL   (2 * 49152)

__global__ __launch_bounds__(256, 2) void proj_kernel()
{
    extern __shared__ __align__(1024) char smem[];
    uint32_t sm = smem_u32(smem);
    int tid = threadIdx.x;
    int wid = tid >> 5, lid = tid & 31;
    int row0 = blockIdx.x * 128;          // v rows
    int n0 = blockIdx.y * 64;             // output features
    int which = blockIdx.z;

    const __nv_bfloat16* Ahi = g_vhi + (size_t)row0 * KDIM;
    const __nv_bfloat16* Alo = g_vlo + (size_t)row0 * KDIM;
    const __nv_bfloat16* Bhi = (which ? g_w2hi : g_w1hi) + (size_t)n0 * KDIM;
    const __nv_bfloat16* Blo = (which ? g_w2lo : g_w1lo) + (size_t)n0 * KDIM;
    __nv_bfloat16* Chi = which ? g_c2hi : g_c1hi;
    __nv_bfloat16* Clo = which ? g_c2lo : g_c1lo;

    auto fill = [&](int buf, int ch) {
        int k0 = ch * PKCH;
        // A tiles: 128 rows x 64 bf16 each (hi, lo) -> 4 x 16B per thread each.
#pragma unroll
        for (int r = 0; r < 4; r++) {
            int idx = r * 256 + tid;          // 0..1023
            int row = idx >> 3, col = (idx & 7) * 8;
            uint32_t off = SW128((uint32_t)(row * 128 + col * 2));
            cp_async16(sm + PSM_A_HI(buf) + off, Ahi + (size_t)row * KDIM + k0 + col);
            cp_async16(sm + PSM_A_LO(buf) + off, Alo + (size_t)row * KDIM + k0 + col);
        }
        // B tiles: 64 rows x 64 bf16 each -> 2 x 16B per thread each.
#pragma unroll
        for (int r = 0; r < 2; r++) {
            int idx = r * 256 + tid;          // 0..511
            int row = idx >> 3, col = (idx & 7) * 8;
            uint32_t off = SW128((uint32_t)(row * 128 + col * 2));
            cp_async16(sm + PSM_B_HI(buf) + off, Bhi + (size_t)row * KDIM + k0 + col);
            cp_async16(sm + PSM_B_LO(buf) + off, Blo + (size_t)row * KDIM + k0 + col);
        }
        CP_COMMIT();
    };

    float acc[4][2][4];
#pragma unroll
    for (int mt = 0; mt < 4; mt++)
#pragma unroll
        for (int nt = 0; nt < 2; nt++)
#pragma unroll
            for (int r = 0; r < 4; r++) acc[mt][nt][r] = 0.0f;

    int wr = wid >> 2;      // 0..1 : 64-row block
    int wc = wid & 3;       // 0..3 : 16-col block
    int lt = lid >> 3, lr = lid & 7;

    fill(0, 0);
    for (int ch = 0; ch < 4; ch++) {
        int buf = ch & 1;
        if (ch < 3) fill(buf ^ 1, ch + 1);
        if (ch < 3) CP_WAIT1(); else CP_WAIT0();
        __syncthreads();

#pragma unroll
        for (int ks = 0; ks < 4; ks++) {
            int k0 = ks * 16;
            uint32_t Ah[4][4], Al[4][4];
#pragma unroll
            for (int mt = 0; mt < 4; mt++) {
                uint32_t off = SW128((uint32_t)(
                    (wr * 64 + mt * 16 + (lt & 1) * 8 + lr) * 128 +
                    (k0 + (lt >> 1) * 8) * 2));
                ldsm_x4(Ah[mt], sm + PSM_A_HI(buf) + off);
                ldsm_x4(Al[mt], sm + PSM_A_LO(buf) + off);
            }
            uint32_t Bh[2][2], Bl[2][2];
#pragma unroll
            for (int nt = 0; nt < 2; nt++) {
                uint32_t off = SW128((uint32_t)(
                    (wc * 16 + nt * 8 + lr) * 128 + (k0 + (lt & 1) * 8) * 2));
                ldsm_x2(Bh[nt], sm + PSM_B_HI(buf) + off);
                ldsm_x2(Bl[nt], sm + PSM_B_LO(buf) + off);
            }
#pragma unroll
            for (int mt = 0; mt < 4; mt++)
#pragma unroll
                for (int nt = 0; nt < 2; nt++) {
                    mma_bf16(acc[mt][nt], Ah[mt], Bh[nt][0], Bh[nt][1]);
                    mma_bf16(acc[mt][nt], Ah[mt], Bl[nt][0], Bl[nt][1]);
                    mma_bf16(acc[mt][nt], Al[mt], Bh[nt][0], Bh[nt][1]);
                }
        }
        __syncthreads();
    }

    // Epilogue: split c into bf16 hi/lo and store.
    int Rb = wr * 64 + (lid >> 2);
    int Cb = wc * 16 + (lid & 3) * 2;
#pragma unroll
    for (int mt = 0; mt < 4; mt++)
#pragma unroll
        for (int h = 0; h < 2; h++) {
            size_t row = (size_t)(row0 + Rb + mt * 16 + h * 8) * KDIM;
#pragma unroll
            for (int nt = 0; nt < 2; nt++) {
                size_t o = row + n0 + Cb + nt * 8;
                float c0 = acc[mt][nt][h * 2 + 0];
                float c1 = acc[mt][nt][h * 2 + 1];
                __nv_bfloat16 h0 = __float2bfloat16(c0);
                __nv_bfloat16 h1 = __float2bfloat16(c1);
                __nv_bfloat16 l0 = __float2bfloat16(c0 - __bfloat162float(h0));
                __nv_bfloat16 l1 = __float2bfloat16(c1 - __bfloat162float(h1));
                *(__nv_bfloat162*)(Chi + o) = __nv_bfloat162(h0, h1);
                *(__nv_bfloat162*)(Clo + o) = __nv_bfloat162(l0, l1);
            }
        }
}

// ---------------------------------------------------------------------------
// Score GEMM (3-term bf16 mma.sync) + fused epilogue.
// CTA 64(n) x 128(m), 128 threads (4 warps), warp tile 64x32.
// KCH=32, SW64 rows (64B). SMEM 2 bufs x 24KB = 48KB -> 3 CTAs/SM.
// ---------------------------------------------------------------------------
#define SKCH 32
#define SSM_BUF(b)  ((b) * 24576)
#define SSM_A_HI(b) (SSM_BUF(b) + 0)
#define SSM_A_LO(b) (SSM_BUF(b) + 4096)
#define SSM_B_HI(b) (SSM_BUF(b) + 8192)
#define SSM_B_LO(b) (SSM_BUF(b) + 16384)
#define SSM_TOTAL   (2 * 24576)

__global__ __launch_bounds__(128, 3) void score_kernel(
    const float* __restrict__ adj,
    float* __restrict__ out)
{
    extern __shared__ __align__(1024) char smem[];
    uint32_t sm = smem_u32(smem);
    int tid = threadIdx.x;
    int wid = tid >> 5, lid = tid & 31;
    int b = blockIdx.z;
    int n0 = blockIdx.x * 64;      // output rows
    int m0 = blockIdx.y * 128;     // output cols

    const size_t boff = (size_t)b * NN * KDIM;
    const __nv_bfloat16* Ahi = g_c1hi + boff + (size_t)n0 * KDIM;
    const __nv_bfloat16* Alo = g_c1lo + boff + (size_t)n0 * KDIM;
    const __nv_bfloat16* Bhi = g_c2hi + boff + (size_t)m0 * KDIM;
    const __nv_bfloat16* Blo = g_c2lo + boff + (size_t)m0 * KDIM;

    auto fill = [&](int buf, int ch) {
        int k0 = ch * SKCH;
        // A tiles: 64 rows x 32 bf16 (64B rows) -> 256 granules -> 2/thread.
#pragma unroll
        for (int r = 0; r < 2; r++) {
            int idx = r * 128 + tid;          // 0..255
            int row = idx >> 2, col = (idx & 3) * 8;
            uint32_t off = SW64((uint32_t)(row * 64 + col * 2));
            cp_async16(sm + SSM_A_HI(buf) + off, Ahi + (size_t)row * KDIM + k0 + col);
            cp_async16(sm + SSM_A_LO(buf) + off, Alo + (size_t)row * KDIM + k0 + col);
        }
        // B tiles: 128 rows x 32 bf16 -> 512 granules -> 4/thread.
#pragma unroll
        for (int r = 0; r < 4; r++) {
            int idx = r * 128 + tid;          // 0..511
            int row = idx >> 2, col = (idx & 3) * 8;
            uint32_t off = SW64((uint32_t)(row * 64 + col * 2));
            cp_async16(sm + SSM_B_HI(buf) + off, Bhi + (size_t)row * KDIM + k0 + col);
            cp_async16(sm + SSM_B_LO(buf) + off, Blo + (size_t)row * KDIM + k0 + col);
        }
        CP_COMMIT();
    };

    float acc[4][4][4];
#pragma unroll
    for (int mt = 0; mt < 4; mt++)
#pragma unroll
        for (int nt = 0; nt < 4; nt++)
#pragma unroll
            for (int r = 0; r < 4; r++) acc[mt][nt][r] = 0.0f;

    int wc = wid;           // 0..3 : 32-col block
    int lt = lid >> 3, lr = lid & 7;

    fill(0, 0);
    for (int ch = 0; ch < 8; ch++) {
        int buf = ch & 1;
        if (ch < 7) fill(buf ^ 1, ch + 1);
        if (ch < 7) CP_WAIT1(); else CP_WAIT0();
        __syncthreads();

#pragma unroll
        for (int ks = 0; ks < 2; ks++) {
            int k0 = ks * 16;
            uint32_t Ah[4][4], Al[4][4];
#pragma unroll
            for (int mt = 0; mt < 4; mt++) {
                uint32_t off = SW64((uint32_t)(
                    (mt * 16 + (lt & 1) * 8 + lr) * 64 +
                    (k0 + (lt >> 1) * 8) * 2));
                ldsm_x4(Ah[mt], sm + SSM_A_HI(buf) + off);
                ldsm_x4(Al[mt], sm + SSM_A_LO(buf) + off);
            }
            uint32_t Bh[4][2], Bl[4][2];
#pragma unroll
            for (int nt = 0; nt < 4; nt++) {
                uint32_t off = SW64((uint32_t)(
                    (wc * 32 + nt * 8 + lr) * 64 + (k0 + (lt & 1) * 8) * 2));
                ldsm_x2(Bh[nt], sm + SSM_B_HI(buf) + off);
                ldsm_x2(Bl[nt], sm + SSM_B_LO(buf) + off);
            }
#pragma unroll
            for (int mt = 0; mt < 4; mt++)
#pragma unroll
                for (int nt = 0; nt < 4; nt++) {
                    mma_bf16(acc[mt][nt], Ah[mt], Bh[nt][0], Bh[nt][1]);
                    mma_bf16(acc[mt][nt], Ah[mt], Bl[nt][0], Bl[nt][1]);
                    mma_bf16(acc[mt][nt], Al[mt], Bh[nt][0], Bh[nt][1]);
                }
        }
        __syncthreads();
    }

    // Fused epilogue straight from accumulators.
    const float* adj_b = adj + ((size_t)b * NN + n0) * NN + m0;
    float* out_b = out + ((size_t)b * NN + n0) * NN + m0;
    int Rb = lid >> 2;
    int Cb = wc * 32 + (lid & 3) * 2;
#pragma unroll
    for (int mt = 0; mt < 4; mt++) {
#pragma unroll
        for (int h = 0; h < 2; h++) {
            size_t row = (size_t)(Rb + mt * 16 + h * 8) * NN;
#pragma unroll
            for (int nt = 0; nt < 4; nt++) {
                size_t o = row + Cb + nt * 8;
                float2 a2 = *(const float2*)(adj_b + o);
                float2 r;
                r.x = epi(acc[mt][nt][h * 2 + 0], a2.x);
                r.y = epi(acc[mt][nt][h * 2 + 1], a2.y);
                *(float2*)(out_b + o) = r;
            }
        }
    }
}

extern "C" void kernel_launch(void* const* d_in, const int* in_sizes, int n_in,
                              void* d_out, int out_size) {
    const float* v   = (const float*)d_in[0];
    const float* adj = (const float*)d_in[1];
    const float* W1  = (const float*)d_in[2];
    const float* W2  = (const float*)d_in[3];
    float* out = (float*)d_out;

    const long adj_elems = 8L * 2048 * 2048;
    long off = (long)out_size - adj_elems;
    if (off < 0) off = 0;
    float* norm_adj = out + off;
    float* out_v = (off > 0) ? out : nullptr;

    // 1. Split v/W into bf16 hi/lo (+ v passthrough copy).
    int split_ctas = (NV / 4 + 2 * (NW / 4) + 255) / 256;
    split_kernel<<<split_ctas, 256>>>(v, W1, W2, out_v);

    // 2. Projections via mma.sync -> g_c{1,2}{hi,lo}.
    cudaFuncSetAttribute(proj_kernel,
                         cudaFuncAttributeMaxDynamicSharedMemorySize, PSM_TOTAL);
    dim3 pgrid(16384 / 128, 256 / 64, 2);
    proj_kernel<<<pgrid, 256, PSM_TOTAL>>>();

    // 3. Score GEMM + fused epilogue (3 CTAs/SM).
    cudaFuncSetAttribute(score_kernel,
                         cudaFuncAttributeMaxDynamicSharedMemorySize, SSM_TOTAL);
    dim3 sgrid(NN / 64, NN / 128, BATCH);
    score_kernel<<<sgrid, 128, SSM_TOTAL>>>(adj, norm_adj);
}

// round 17
// speedup vs baseline: 1.5026x; 1.0039x over previous
#include <cuda_runtime.h>
#include <cuda_bf16.h>
#include <cstdint>

// ---------------- problem sizes ----------------
#define BATCH 8
#define NN    2048
#define KDIM  256
#define NV    (BATCH * NN * KDIM)   // 4,194,304 v elems
#define NW    (256 * 256)           // W elems

// bf16 hi/lo splits of inputs and projections.
__device__ __align__(16) __nv_bfloat16 g_vhi[NV],  g_vlo[NV];
__device__ __align__(16) __nv_bfloat16 g_w1hi[NW], g_w1lo[NW];
__device__ __align__(16) __nv_bfloat16 g_w2hi[NW], g_w2lo[NW];
__device__ __align__(16) __nv_bfloat16 g_c1hi[NV], g_c1lo[NV];
__device__ __align__(16) __nv_bfloat16 g_c2hi[NV], g_c2lo[NV];

// ---------------- helpers ----------------
__device__ __forceinline__ uint32_t smem_u32(const void* p) {
    uint32_t a;
    asm("{ .reg .u64 t; cvta.to.shared.u64 t, %1; cvt.u32.u64 %0, t; }"
        : "=r"(a) : "l"(p));
    return a;
}

#define SW128(off) ((off) ^ (((off) >> 3) & 0x70))   // 128B-row swizzle
#define SW64(off)  ((off) ^ (((off) >> 3) & 0x30))   // 64B-row swizzle

__device__ __forceinline__ void ldsm_x4(uint32_t (&r)[4], uint32_t addr) {
    asm volatile("ldmatrix.sync.aligned.m8n8.x4.shared.b16 {%0,%1,%2,%3}, [%4];"
        : "=r"(r[0]), "=r"(r[1]), "=r"(r[2]), "=r"(r[3]) : "r"(addr));
}
__device__ __forceinline__ void ldsm_x2(uint32_t (&r)[2], uint32_t addr) {
    asm volatile("ldmatrix.sync.aligned.m8n8.x2.shared.b16 {%0,%1}, [%2];"
        : "=r"(r[0]), "=r"(r[1]) : "r"(addr));
}
__device__ __forceinline__ void mma_bf16(float (&d)[4], const uint32_t (&a)[4],
                                         const uint32_t b0, const uint32_t b1) {
    asm volatile(
        "mma.sync.aligned.m16n8k16.row.col.f32.bf16.bf16.f32 "
        "{%0,%1,%2,%3}, {%4,%5,%6,%7}, {%8,%9}, {%0,%1,%2,%3};"
        : "+f"(d[0]), "+f"(d[1]), "+f"(d[2]), "+f"(d[3])
        : "r"(a[0]), "r"(a[1]), "r"(a[2]), "r"(a[3]), "r"(b0), "r"(b1));
}
__device__ __forceinline__ void cp_async16(uint32_t dst, const void* src) {
    asm volatile("cp.async.cg.shared.global [%0], [%1], 16;" :: "r"(dst), "l"(src));
}
#define CP_COMMIT() asm volatile("cp.async.commit_group;" ::: "memory")
#define CP_WAIT1()  asm volatile("cp.async.wait_group 1;" ::: "memory")
#define CP_WAIT0()  asm volatile("cp.async.wait_group 0;" ::: "memory")

// ---------------- elementwise epilogue (3 MUFU) ----------------
__device__ __forceinline__ float epi(float s, float a) {
    float t = __expf(fminf(-s, 80.0f));
    float u = 1.0f + t;
    float q = __fdividef(u, fmaf(1e-5f, u, 100.0f));
    q *= 0.70710678f;
    float cc = q * q;                  // = 1/(2 c^2)
    return __expf(-(a * a * cc));
}

__device__ __forceinline__ void split_store(__nv_bfloat16* hi, __nv_bfloat16* lo,
                                            int t, float4 x) {
    float xs[4] = {x.x, x.y, x.z, x.w};
    __nv_bfloat16 h[4], l[4];
#pragma unroll
    for (int j = 0; j < 4; j++) {
        h[j] = __float2bfloat16(xs[j]);
        l[j] = __float2bfloat16(xs[j] - __bfloat162float(h[j]));
    }
    *(__nv_bfloat162*)(hi + 4 * t)     = __nv_bfloat162(h[0], h[1]);
    *(__nv_bfloat162*)(hi + 4 * t + 2) = __nv_bfloat162(h[2], h[3]);
    *(__nv_bfloat162*)(lo + 4 * t)     = __nv_bfloat162(l[0], l[1]);
    *(__nv_bfloat162*)(lo + 4 * t + 2) = __nv_bfloat162(l[2], l[3]);
}

// ---------------------------------------------------------------------------
// Split kernel: v -> (g_vhi, g_vlo) + v passthrough copy; W1/W2 -> splits.
// (Also serves as the machine-state control: fixed 100MB traffic, ~9.5us
// on a healthy container.)
// ---------------------------------------------------------------------------
__global__ __launch_bounds__(256) void split_kernel(
    const float* __restrict__ v,
    const float* __restrict__ W1,
    const float* __restrict__ W2,
    float* __restrict__ out_v)
{
    const int NV4 = NV / 4, NW4 = NW / 4;
    int t = blockIdx.x * 256 + threadIdx.x;
    if (t < NV4) {
        float4 x = ((const float4*)v)[t];
        if (out_v) ((float4*)out_v)[t] = x;
        split_store(g_vhi, g_vlo, t, x);
    } else if (t < NV4 + NW4) {
        int i = t - NV4;
        split_store(g_w1hi, g_w1lo, i, ((const float4*)W1)[i]);
    } else if (t < NV4 + 2 * NW4) {
        int i = t - NV4 - NW4;
        split_store(g_w2hi, g_w2lo, i, ((const float4*)W2)[i]);
    }
}

// ---------------------------------------------------------------------------
// Projection via mma.sync (3-term bf16): c = v @ W^T, K=256.
// CTA 128 rows x 64 cols, 8 warps (2x4), warp tile 64x16 (4x2 m16n8k16).
// KCH=64, SW128 rows, double-buffered cp.async. 2 CTAs/SM.
// ---------------------------------------------------------------------------
#define PKCH 64
#define PSM_BUF(b) ((b) * 49152)
#define PSM_A_HI(b) (PSM_BUF(b) + 0)
#define PSM_A_LO(b) (PSM_BUF(b) + 16384)
#define PSM_B_HI(b) (PSM_BUF(b) + 32768)
#define PSM_B_LO(b) (PSM_BUF(b) + 40960)
#define PSM_TOTAL   (2 * 49152)

__global__ __launch_bounds__(256, 2) void proj_kernel()
{
    extern __shared__ __align__(1024) char smem[];
    uint32_t sm = smem_u32(smem);
    int tid = threadIdx.x;
    int wid = tid >> 5, lid = tid & 31;
    int row0 = blockIdx.x * 128;          // v rows
    int n0 = blockIdx.y * 64;             // output features
    int which = blockIdx.z;

    const __nv_bfloat16* Ahi = g_vhi + (size_t)row0 * KDIM;
    const __nv_bfloat16* Alo = g_vlo + (size_t)row0 * KDIM;
    const __nv_bfloat16* Bhi = (which ? g_w2hi : g_w1hi) + (size_t)n0 * KDIM;
    const __nv_bfloat16* Blo = (which ? g_w2lo : g_w1lo) + (size_t)n0 * KDIM;
    __nv_bfloat16* Chi = which ? g_c2hi : g_c1hi;
    __nv_bfloat16* Clo = which ? g_c2lo : g_c1lo;

    auto fill = [&](int buf, int ch) {
        int k0 = ch * PKCH;
        // A tiles: 128 rows x 64 bf16 each (hi, lo) -> 4 x 16B per thread each.
#pragma unroll
        for (int r = 0; r < 4; r++) {
            int idx = r * 256 + tid;          // 0..1023
            int row = idx >> 3, col = (idx & 7) * 8;
            uint32_t off = SW128((uint32_t)(row * 128 + col * 2));
            cp_async16(sm + PSM_A_HI(buf) + off, Ahi + (size_t)row * KDIM + k0 + col);
            cp_async16(sm + PSM_A_LO(buf) + off, Alo + (size_t)row * KDIM + k0 + col);
        }
        // B tiles: 64 rows x 64 bf16 each -> 2 x 16B per thread each.
#pragma unroll
        for (int r = 0; r < 2; r++) {
            int idx = r * 256 + tid;          // 0..511
            int row = idx >> 3, col = (idx & 7) * 8;
            uint32_t off = SW128((uint32_t)(row * 128 + col * 2));
            cp_async16(sm + PSM_B_HI(buf) + off, Bhi + (size_t)row * KDIM + k0 + col);
            cp_async16(sm + PSM_B_LO(buf) + off, Blo + (size_t)row * KDIM + k0 + col);
        }
        CP_COMMIT();
    };

    float acc[4][2][4];
#pragma unroll
    for (int mt = 0; mt < 4; mt++)
#pragma unroll
        for (int nt = 0; nt < 2; nt++)
#pragma unroll
            for (int r = 0; r < 4; r++) acc[mt][nt][r] = 0.0f;

    int wr = wid >> 2;      // 0..1 : 64-row block
    int wc = wid & 3;       // 0..3 : 16-col block
    int lt = lid >> 3, lr = lid & 7;

    fill(0, 0);
    for (int ch = 0; ch < 4; ch++) {
        int buf = ch & 1;
        if (ch < 3) fill(buf ^ 1, ch + 1);
        if (ch < 3) CP_WAIT1(); else CP_WAIT0();
        __syncthreads();

#pragma unroll
        for (int ks = 0; ks < 4; ks++) {
            int k0 = ks * 16;
            uint32_t Ah[4][4], Al[4][4];
#pragma unroll
            for (int mt = 0; mt < 4; mt++) {
                uint32_t off = SW128((uint32_t)(
                    (wr * 64 + mt * 16 + (lt & 1) * 8 + lr) * 128 +
                    (k0 + (lt >> 1) * 8) * 2));
                ldsm_x4(Ah[mt], sm + PSM_A_HI(buf) + off);
                ldsm_x4(Al[mt], sm + PSM_A_LO(buf) + off);
            }
            uint32_t Bh[2][2], Bl[2][2];
#pragma unroll
            for (int nt = 0; nt < 2; nt++) {
                uint32_t off = SW128((uint32_t)(
                    (wc * 16 + nt * 8 + lr) * 128 + (k0 + (lt & 1) * 8) * 2));
                ldsm_x2(Bh[nt], sm + PSM_B_HI(buf) + off);
                ldsm_x2(Bl[nt], sm + PSM_B_LO(buf) + off);
            }
#pragma unroll
            for (int mt = 0; mt < 4; mt++)
#pragma unroll
                for (int nt = 0; nt < 2; nt++) {
                    mma_bf16(acc[mt][nt], Ah[mt], Bh[nt][0], Bh[nt][1]);
                    mma_bf16(acc[mt][nt], Ah[mt], Bl[nt][0], Bl[nt][1]);
                    mma_bf16(acc[mt][nt], Al[mt], Bh[nt][0], Bh[nt][1]);
                }
        }
        __syncthreads();
    }

    // Epilogue: split c into bf16 hi/lo and store.
    int Rb = wr * 64 + (lid >> 2);
    int Cb = wc * 16 + (lid & 3) * 2;
#pragma unroll
    for (int mt = 0; mt < 4; mt++)
#pragma unroll
        for (int h = 0; h < 2; h++) {
            size_t row = (size_t)(row0 + Rb + mt * 16 + h * 8) * KDIM;
#pragma unroll
            for (int nt = 0; nt < 2; nt++) {
                size_t o = row + n0 + Cb + nt * 8;
                float c0 = acc[mt][nt][h * 2 + 0];
                float c1 = acc[mt][nt][h * 2 + 1];
                __nv_bfloat16 h0 = __float2bfloat16(c0);
                __nv_bfloat16 h1 = __float2bfloat16(c1);
                __nv_bfloat16 l0 = __float2bfloat16(c0 - __bfloat162float(h0));
                __nv_bfloat16 l1 = __float2bfloat16(c1 - __bfloat162float(h1));
                *(__nv_bfloat162*)(Chi + o) = __nv_bfloat162(h0, h1);
                *(__nv_bfloat162*)(Clo + o) = __nv_bfloat162(l0, l1);
            }
        }
}

// ---------------------------------------------------------------------------
// Score GEMM (3-term bf16 mma.sync) + fused epilogue.
// CTA 64(n) x 128(m), 128 threads (4 warps), warp tile 64x32.
// KCH=32, SW64 rows (64B). SMEM 2 bufs x 24KB = 48KB -> 3 CTAs/SM.
// ---------------------------------------------------------------------------
#define SKCH 32
#define SSM_BUF(b)  ((b) * 24576)
#define SSM_A_HI(b) (SSM_BUF(b) + 0)
#define SSM_A_LO(b) (SSM_BUF(b) + 4096)
#define SSM_B_HI(b) (SSM_BUF(b) + 8192)
#define SSM_B_LO(b) (SSM_BUF(b) + 16384)
#define SSM_TOTAL   (2 * 24576)

__global__ __launch_bounds__(128, 3) void score_kernel(
    const float* __restrict__ adj,
    float* __restrict__ out)
{
    extern __shared__ __align__(1024) char smem[];
    uint32_t sm = smem_u32(smem);
    int tid = threadIdx.x;
    int wid = tid >> 5, lid = tid & 31;
    int b = blockIdx.z;
    int n0 = blockIdx.x * 64;      // output rows
    int m0 = blockIdx.y * 128;     // output cols

    const size_t boff = (size_t)b * NN * KDIM;
    const __nv_bfloat16* Ahi = g_c1hi + boff + (size_t)n0 * KDIM;
    const __nv_bfloat16* Alo = g_c1lo + boff + (size_t)n0 * KDIM;
    const __nv_bfloat16* Bhi = g_c2hi + boff + (size_t)m0 * KDIM;
    const __nv_bfloat16* Blo = g_c2lo + boff + (size_t)m0 * KDIM;

    auto fill = [&](int buf, int ch) {
        int k0 = ch * SKCH;
        // A tiles: 64 rows x 32 bf16 (64B rows) -> 256 granules -> 2/thread.
#pragma unroll
        for (int r = 0; r < 2; r++) {
            int idx = r * 128 + tid;          // 0..255
            int row = idx >> 2, col = (idx & 3) * 8;
            uint32_t off = SW64((uint32_t)(row * 64 + col * 2));
            cp_async16(sm + SSM_A_HI(buf) + off, Ahi + (size_t)row * KDIM + k0 + col);
            cp_async16(sm + SSM_A_LO(buf) + off, Alo + (size_t)row * KDIM + k0 + col);
        }
        // B tiles: 128 rows x 32 bf16 -> 512 granules -> 4/thread.
#pragma unroll
        for (int r = 0; r < 4; r++) {
            int idx = r * 128 + tid;          // 0..511
            int row = idx >> 2, col = (idx & 3) * 8;
            uint32_t off = SW64((uint32_t)(row * 64 + col * 2));
            cp_async16(sm + SSM_B_HI(buf) + off, Bhi + (size_t)row * KDIM + k0 + col);
            cp_async16(sm + SSM_B_LO(buf) + off, Blo + (size_t)row * KDIM + k0 + col);
        }
        CP_COMMIT();
    };

    float acc[4][4][4];
#pragma unroll
    for (int mt = 0; mt < 4; mt++)
#pragma unroll
        for (int nt = 0; nt < 4; nt++)
#pragma unroll
            for (int r = 0; r < 4; r++) acc[mt][nt][r] = 0.0f;

    int wc = wid;           // 0..3 : 32-col block
    int lt = lid >> 3, lr = lid & 7;

    fill(0, 0);
    for (int ch = 0; ch < 8; ch++) {
        int buf = ch & 1;
        if (ch < 7) fill(buf ^ 1, ch + 1);
        if (ch < 7) CP_WAIT1(); else CP_WAIT0();
        __syncthreads();

#pragma unroll
        for (int ks = 0; ks < 2; ks++) {
            int k0 = ks * 16;
            uint32_t Ah[4][4], Al[4][4];
#pragma unroll
            for (int mt = 0; mt < 4; mt++) {
                uint32_t off = SW64((uint32_t)(
                    (mt * 16 + (lt & 1) * 8 + lr) * 64 +
                    (k0 + (lt >> 1) * 8) * 2));
                ldsm_x4(Ah[mt], sm + SSM_A_HI(buf) + off);
                ldsm_x4(Al[mt], sm + SSM_A_LO(buf) + off);
            }
            uint32_t Bh[4][2], Bl[4][2];
#pragma unroll
            for (int nt = 0; nt < 4; nt++) {
                uint32_t off = SW64((uint32_t)(
                    (wc * 32 + nt * 8 + lr) * 64 + (k0 + (lt & 1) * 8) * 2));
                ldsm_x2(Bh[nt], sm + SSM_B_HI(buf) + off);
                ldsm_x2(Bl[nt], sm + SSM_B_LO(buf) + off);
            }
#pragma unroll
            for (int mt = 0; mt < 4; mt++)
#pragma unroll
                for (int nt = 0; nt < 4; nt++) {
                    mma_bf16(acc[mt][nt], Ah[mt], Bh[nt][0], Bh[nt][1]);
                    mma_bf16(acc[mt][nt], Ah[mt], Bl[nt][0], Bl[nt][1]);
                    mma_bf16(acc[mt][nt], Al[mt], Bh[nt][0], Bh[nt][1]);
                }
        }
        __syncthreads();
    }

    // Fused epilogue straight from accumulators.
    const float* adj_b = adj + ((size_t)b * NN + n0) * NN + m0;
    float* out_b = out + ((size_t)b * NN + n0) * NN + m0;
    int Rb = lid >> 2;
    int Cb = wc * 32 + (lid & 3) * 2;
#pragma unroll
    for (int mt = 0; mt < 4; mt++) {
#pragma unroll
        for (int h = 0; h < 2; h++) {
            size_t row = (size_t)(Rb + mt * 16 + h * 8) * NN;
#pragma unroll
            for (int nt = 0; nt < 4; nt++) {
                size_t o = row + Cb + nt * 8;
                float2 a2 = *(const float2*)(adj_b + o);
                float2 r;
                r.x = epi(acc[mt][nt][h * 2 + 0], a2.x);
                r.y = epi(acc[mt][nt][h * 2 + 1], a2.y);
                *(float2*)(out_b + o) = r;
            }
        }
    }
}

extern "C" void kernel_launch(void* const* d_in, const int* in_sizes, int n_in,
                              void* d_out, int out_size) {
    const float* v   = (const float*)d_in[0];
    const float* adj = (const float*)d_in[1];
    const float* W1  = (const float*)d_in[2];
    const float* W2  = (const float*)d_in[3];
    float* out = (float*)d_out;

    const long adj_elems = 8L * 2048 * 2048;
    long off = (long)out_size - adj_elems;
    if (off < 0) off = 0;
    float* norm_adj = out + off;
    float* out_v = (off > 0) ? out : nullptr;

    // 1. Split v/W into bf16 hi/lo (+ v passthrough copy).
    int split_ctas = (NV / 4 + 2 * (NW / 4) + 255) / 256;
    split_kernel<<<split_ctas, 256>>>(v, W1, W2, out_v);

    // 2. Projections via mma.sync -> g_c{1,2}{hi,lo}.
    cudaFuncSetAttribute(proj_kernel,
                         cudaFuncAttributeMaxDynamicSharedMemorySize, PSM_TOTAL);
    dim3 pgrid(16384 / 128, 256 / 64, 2);
    proj_kernel<<<pgrid, 256, PSM_TOTAL>>>();

    // 3. Score GEMM + fused epilogue (3 CTAs/SM).
    cudaFuncSetAttribute(score_kernel,
                         cudaFuncAttributeMaxDynamicSharedMemorySize, SSM_TOTAL);
    dim3 sgrid(NN / 64, NN / 128, BATCH);
    score_kernel<<<sgrid, 128, SSM_TOTAL>>>(adj, norm_adj);
}